// round 11
// baseline (speedup 1.0000x reference)
#include <cuda_runtime.h>
#include <cuda_bf16.h>

#define EPS 1e-16f
#define W 1024
#define H 1024
#define ROWS 4          // output rows per block
#define TPB 256         // 256 threads * 4 px = 1024 = full row width

// out(x,y) = (dxf+dyf)*invF - dxf(x-1,y)*invF(x-1,y) - dyf(x,y-1)*invF(x,y-1)
// (G(x,y)=F(x-1,y), H(x,y)=F(x,y-1) on the reflect-padded grid).
// Tile staged in smem; left-column F-term recomputed per thread (no 2nd barrier).
__global__ __launch_bounds__(TPB, 8)
void curvature_kernel(const float* __restrict__ u, float* __restrict__ out) {
    __shared__ float sm[ROWS + 2][W];       // 24 KB

    const int tile = blockIdx.x;            // b * (H/ROWS) + row-tile
    const int b    = tile >> 8;             // H/ROWS = 256 tiles per image
    const int x0   = (tile & 255) * ROWS;   // first output row
    const int t    = threadIdx.x;
    const int y    = t * 4;                 // first output col (float4 granule)

    const float* ub = u   + (size_t)b * (H * W);
    float*       ob = out + (size_t)b * (H * W);

    // ---- stage 6 padded rows (x0-1 .. x0+4), reflect-clamped in x ----
    #pragma unroll
    for (int m = 0; m < ROWS + 2; ++m) {
        int r = x0 - 1 + m;
        r = (r < 0) ? 1 : ((r >= H) ? (H - 2) : r);
        *reinterpret_cast<float4*>(&sm[m][y]) =
            *reinterpret_cast<const float4*>(ub + (size_t)r * W + y);
    }
    __syncthreads();

    // reflect-clamped side columns (pure index math, no divergence)
    const int cL = (y == 0)     ? 1       : (y - 1);
    const int cR = (y + 4 == W) ? (W - 2) : (y + 4);

    // rolling state
    float4 q0 = *reinterpret_cast<const float4*>(&sm[0][y]);
    float  l0 = sm[0][cL];
    float  Ap0, Ap1, Ap2, Ap3;              // A = dxf*invF from previous F-row

    #pragma unroll
    for (int k = 0; k <= ROWS; ++k) {
        const float4 q1 = *reinterpret_cast<const float4*>(&sm[k + 1][y]);
        const float  l1 = sm[k + 1][cL];
        const float  r0 = sm[k][cR];

        // F-terms on padded row x0-1+k, cols y-1 .. y+3
        const float dxm = l1 - l0,   dym = q0.x - l0;
        const float iFm = rsqrtf(fmaf(dxm, dxm, fmaf(dym, dym, EPS)));
        const float Bm  = dym * iFm;                     // B at col y-1

        const float dx0 = q1.x - q0.x, dy0 = q0.y - q0.x;
        const float iF0 = rsqrtf(fmaf(dx0, dx0, fmaf(dy0, dy0, EPS)));
        const float dx1 = q1.y - q0.y, dy1 = q0.z - q0.y;
        const float iF1 = rsqrtf(fmaf(dx1, dx1, fmaf(dy1, dy1, EPS)));
        const float dx2 = q1.z - q0.z, dy2 = q0.w - q0.z;
        const float iF2 = rsqrtf(fmaf(dx2, dx2, fmaf(dy2, dy2, EPS)));
        const float dx3 = q1.w - q0.w, dy3 = r0 - q0.w;
        const float iF3 = rsqrtf(fmaf(dx3, dx3, fmaf(dy3, dy3, EPS)));

        if (k > 0) {
            float4 o;
            o.x = (dx0 + dy0) * iF0 - Ap0 - Bm;
            o.y = (dx1 + dy1) * iF1 - Ap1 - dy0 * iF0;
            o.z = (dx2 + dy2) * iF2 - Ap2 - dy1 * iF1;
            o.w = (dx3 + dy3) * iF3 - Ap3 - dy2 * iF2;
            *reinterpret_cast<float4*>(ob + (size_t)(x0 + k - 1) * W + y) = o;
        }
        Ap0 = dx0 * iF0; Ap1 = dx1 * iF1; Ap2 = dx2 * iF2; Ap3 = dx3 * iF3;
        q0 = q1; l0 = l1;
    }
}

extern "C" void kernel_launch(void* const* d_in, const int* in_sizes, int n_in,
                              void* d_out, int out_size) {
    const float* u = (const float*)d_in[0];
    float* out = (float*)d_out;
    const int batch = in_sizes[0] / (H * W);   // 16
    const int blocks = batch * (H / ROWS);     // 4096
    curvature_kernel<<<blocks, TPB>>>(u, out);
}

// round 12
// speedup vs baseline: 1.7222x; 1.7222x over previous
#include <cuda_runtime.h>
#include <cuda_bf16.h>

#define EPS 1e-16f
#define W 1024
#define H 1024
#define ROWS 4          // output rows per thread/block
#define TPB 256         // 256 threads * 4 px = 1024 = full row width

// out(x,y) = (dxf+dyf)*invF - dxf(x-1,y)*invF(x-1,y) - dyf(x,y-1)*invF(x,y-1)
// (G(x,y)=F(x-1,y), H(x,y)=F(x,y-1) on the reflect-padded grid).
// Rows live in registers; only 4B-stride edge columns go through smem.
__global__ __launch_bounds__(TPB, 6)
void curvature_kernel(const float* __restrict__ u, float* __restrict__ out) {
    const int tile = blockIdx.x;            // b * (H/ROWS) + row-tile
    const int b    = tile >> 8;             // H/ROWS = 256 tiles per image
    const int x0   = (tile & 255) * ROWS;   // first output row
    const int t    = threadIdx.x;
    const int y    = t * 4;                 // first output col (float4 granule)

    const float* ub = u   + (size_t)b * (H * W);
    float*       ob = out + (size_t)b * (H * W);

    // edgeL[k][t] = rows[k][3]  (this quad's right edge  -> left halo of t+1)
    // edgeR[k][t] = rows[k][0]  (this quad's left edge   -> right halo of t-1)
    __shared__ float edgeL[ROWS + 2][TPB];
    __shared__ float edgeR[ROWS + 1][TPB];

    // ---- 6 row-vectors (padded rows x0-1 .. x0+4), reflect-clamped in x ----
    float rows[ROWS + 2][4];
    #pragma unroll
    for (int m = 0; m < ROWS + 2; ++m) {
        int r = x0 - 1 + m;
        r = (r < 0) ? 1 : ((r >= H) ? (H - 2) : r);
        float4 v = *reinterpret_cast<const float4*>(ub + (size_t)r * W + y);
        rows[m][0] = v.x; rows[m][1] = v.y; rows[m][2] = v.z; rows[m][3] = v.w;
    }

    // ---- publish edges (fire-and-forget STS), one barrier ----
    #pragma unroll
    for (int k = 0; k < ROWS + 2; ++k) edgeL[k][t] = rows[k][3];
    #pragma unroll
    for (int k = 0; k < ROWS + 1; ++k) edgeR[k][t] = rows[k][0];
    __syncthreads();

    const int tm = (t == 0)       ? 0       : (t - 1);
    const int tp = (t == TPB - 1) ? TPB - 1 : (t + 1);

    // L[k] = u~[x0-1+k, y-1] ; reflect at image edge: col -1 -> col 1 (own reg)
    float l0 = (t == 0) ? rows[0][1] : edgeL[0][tm];
    float Ap0, Ap1, Ap2, Ap3;               // A = dxf*invF from previous F-row

    #pragma unroll
    for (int k = 0; k <= ROWS; ++k) {
        float l1 = (t == 0)       ? rows[k + 1][1] : edgeL[k + 1][tm];
        float r0 = (t == TPB - 1) ? rows[k][2]     : edgeR[k][tp];  // col W -> W-2

        // F-terms on padded row x0-1+k, cols y-1 .. y+3
        const float dxm = l1 - l0,        dym = rows[k][0] - l0;
        const float iFm = rsqrtf(fmaf(dxm, dxm, fmaf(dym, dym, EPS)));
        const float Bm  = dym * iFm;                      // B at col y-1

        const float dx0 = rows[k + 1][0] - rows[k][0], dy0 = rows[k][1] - rows[k][0];
        const float iF0 = rsqrtf(fmaf(dx0, dx0, fmaf(dy0, dy0, EPS)));
        const float dx1 = rows[k + 1][1] - rows[k][1], dy1 = rows[k][2] - rows[k][1];
        const float iF1 = rsqrtf(fmaf(dx1, dx1, fmaf(dy1, dy1, EPS)));
        const float dx2 = rows[k + 1][2] - rows[k][2], dy2 = rows[k][3] - rows[k][2];
        const float iF2 = rsqrtf(fmaf(dx2, dx2, fmaf(dy2, dy2, EPS)));
        const float dx3 = rows[k + 1][3] - rows[k][3], dy3 = r0 - rows[k][3];
        const float iF3 = rsqrtf(fmaf(dx3, dx3, fmaf(dy3, dy3, EPS)));

        if (k > 0) {
            float4 o;
            o.x = (dx0 + dy0) * iF0 - Ap0 - Bm;
            o.y = (dx1 + dy1) * iF1 - Ap1 - dy0 * iF0;
            o.z = (dx2 + dy2) * iF2 - Ap2 - dy1 * iF1;
            o.w = (dx3 + dy3) * iF3 - Ap3 - dy2 * iF2;
            *reinterpret_cast<float4*>(ob + (size_t)(x0 + k - 1) * W + y) = o;
        }
        Ap0 = dx0 * iF0; Ap1 = dx1 * iF1; Ap2 = dx2 * iF2; Ap3 = dx3 * iF3;
        l0 = l1;
    }
}

extern "C" void kernel_launch(void* const* d_in, const int* in_sizes, int n_in,
                              void* d_out, int out_size) {
    const float* u = (const float*)d_in[0];
    float* out = (float*)d_out;
    const int batch = in_sizes[0] / (H * W);   // 16
    const int blocks = batch * (H / ROWS);     // 4096
    curvature_kernel<<<blocks, TPB>>>(u, out);
}